// round 5
// baseline (speedup 1.0000x reference)
#include <cuda_runtime.h>
#include <cuda_bf16.h>
#include <math.h>
#include <stdint.h>

// Problem shape (fixed by the dataset)
#define BB 8
#define SS 2048
#define DD 1024

// Scratch (device globals — allocation-guard-safe)
__device__ float g_proj[(size_t)BB * SS * DD];   // proj = X@W^T + b
__device__ float g_xt[(size_t)BB * SS * DD];     // XT[b] = X[b]^T

// ============================================================
// Tensor-core NT GEMM via mma.sync bf16 (plain sm_103 target; tcgen05
// unavailable in this toolchain's PTX target).
// fp32 emulated as bf16x2 split, 3 products (11,12,21).
// CTA tile 128x128, K-chunk 64, double-buffered smem.
// R5 changes vs R4:
//   * product loop OUTERMOST per k-step (acc reuse distance 8, no RAW chains)
//   * 512 threads / 16 warps, 32x32 warp tiles (4 warps/SMSP latency hiding)
// ============================================================

#define TILE_B  16384           // one 128x64 bf16 tile (128B rows, SW128)
#define BUF_B   65536           // A0,A1,B0,B1
#define GEMM_SMEM (2 * BUF_B)   // 128 KB

__device__ __forceinline__ uint32_t smem_u32(const void* p) {
    uint32_t a;
    asm("{ .reg .u64 t; cvta.to.shared.u64 t, %1; cvt.u32.u64 %0, t; }" : "=r"(a) : "l"(p));
    return a;
}
__device__ __forceinline__ uint32_t sw128(uint32_t off) {
    return off ^ ((off >> 3) & 0x70);
}
__device__ __forceinline__ void ldsm_x4(uint32_t& r0, uint32_t& r1, uint32_t& r2, uint32_t& r3,
                                        uint32_t addr) {
    asm volatile("ldmatrix.sync.aligned.m8n8.x4.shared.b16 {%0,%1,%2,%3}, [%4];"
                 : "=r"(r0), "=r"(r1), "=r"(r2), "=r"(r3) : "r"(addr));
}
__device__ __forceinline__ void mma16816(float* d, const uint32_t* a, const uint32_t* b) {
    asm volatile(
        "mma.sync.aligned.m16n8k16.row.col.f32.bf16.bf16.f32 "
        "{%0,%1,%2,%3}, {%4,%5,%6,%7}, {%8,%9}, {%0,%1,%2,%3};"
        : "+f"(d[0]), "+f"(d[1]), "+f"(d[2]), "+f"(d[3])
        : "r"(a[0]), "r"(a[1]), "r"(a[2]), "r"(a[3]), "r"(b[0]), "r"(b[1]));
}

// Split one float4 into two bf16x4 (hi, lo-residual) packed as 2x uint32
__device__ __forceinline__ void split2(const float4& v, uint2& hi, uint2& lo) {
    __nv_bfloat162 h0 = __floats2bfloat162_rn(v.x, v.y);
    __nv_bfloat162 h1 = __floats2bfloat162_rn(v.z, v.w);
    float r0 = v.x - __bfloat162float(__low2bfloat16(h0));
    float r1 = v.y - __bfloat162float(__high2bfloat16(h0));
    float r2 = v.z - __bfloat162float(__low2bfloat16(h1));
    float r3 = v.w - __bfloat162float(__high2bfloat16(h1));
    __nv_bfloat162 l0 = __floats2bfloat162_rn(r0, r1);
    __nv_bfloat162 l1 = __floats2bfloat162_rn(r2, r3);
    hi.x = *reinterpret_cast<uint32_t*>(&h0);
    hi.y = *reinterpret_cast<uint32_t*>(&h1);
    lo.x = *reinterpret_cast<uint32_t*>(&l0);
    lo.y = *reinterpret_cast<uint32_t*>(&l1);
}

__global__ __launch_bounds__(512, 1) void gemm_nt_mma(
    const float* __restrict__ A, const float* __restrict__ B,
    float* __restrict__ C, const float* __restrict__ bias,
    int M, int N, int K,
    long long strA, long long strB, long long strC)
{
    extern __shared__ __align__(1024) char smem[];
    const uint32_t sb = smem_u32(smem);
    const int tid = threadIdx.x, wid = tid >> 5, lane = tid & 31;
    const int row0 = blockIdx.y * 128, col0 = blockIdx.x * 128;
    const float* Ab = A + (long long)blockIdx.z * strA;
    const float* Bb = B + (long long)blockIdx.z * strB;
    float*       Cb = C + (long long)blockIdx.z * strC;

    // 4m x 4n warp grid, 32x32 warp tiles
    const int wm = wid & 3, wn = wid >> 2;
    const int m0w = wm * 32, n0w = wn * 32;

    // --- loader indexing (per 32-col sub-chunk): thread covers 8 floats ---
    const int ldr  = tid >> 2;                   // row 0..127
    const int ldc0 = (tid & 3) * 8;              // col base within 32

    // --- ldmatrix lane addressing ---
    const uint32_t a_lrow = (uint32_t)(lane & 15);
    const uint32_t a_lc8  = (uint32_t)(lane >> 4) * 8;
    const uint32_t b_lrow = (uint32_t)((lane & 7) + ((lane >> 4) & 1) * 8);
    const uint32_t b_lk8  = (uint32_t)((lane >> 3) & 1) * 8;

    float acc[2][4][4];
#pragma unroll
    for (int i = 0; i < 2; i++)
#pragma unroll
        for (int j = 0; j < 4; j++)
#pragma unroll
            for (int q = 0; q < 4; q++) acc[i][j][q] = 0.f;

    const int NCH = K >> 6;

    auto ldg_sub = [&](int ch, int sub, float4* av, float4* bv) {
        const int k0 = (ch << 6) + sub * 32 + ldc0;
        const float* pa = Ab + (size_t)(row0 + ldr) * K + k0;
        const float* pb = Bb + (size_t)(col0 + ldr) * K + k0;
        av[0] = *(const float4*)pa;       av[1] = *(const float4*)(pa + 4);
        bv[0] = *(const float4*)pb;       bv[1] = *(const float4*)(pb + 4);
    };
    auto sts_sub = [&](uint32_t base, int sub, const float4* av, const float4* bv) {
#pragma unroll
        for (int q = 0; q < 2; q++) {
            uint32_t off = (uint32_t)(ldr * 128 + (sub * 32 + ldc0 + 4 * q) * 2);
            uint32_t sw  = sw128(off);
            uint2 hi, lo;
            split2(av[q], hi, lo);
            *reinterpret_cast<uint2*>(smem + (base) + sw)              = hi;  // A0
            *reinterpret_cast<uint2*>(smem + (base + TILE_B) + sw)     = lo;  // A1
            split2(bv[q], hi, lo);
            *reinterpret_cast<uint2*>(smem + (base + 2 * TILE_B) + sw) = hi;  // B0
            *reinterpret_cast<uint2*>(smem + (base + 3 * TILE_B) + sw) = lo;  // B1
        }
    };
    // One k-step (k16): load frags for both levels, then 3 products with the
    // product loop OUTERMOST (acc reuse distance = 8 MMAs -> no RAW stalls).
    auto mma_ks = [&](uint32_t base, int ks) {
        uint32_t aF[2][2][4], bF[2][4][2];
#pragma unroll
        for (int lv = 0; lv < 2; lv++) {
            uint32_t tb = base + lv * TILE_B;
#pragma unroll
            for (int mf = 0; mf < 2; mf++) {
                uint32_t off = (uint32_t)((m0w + mf * 16 + a_lrow) * 128
                                          + (ks * 16 + a_lc8) * 2);
                ldsm_x4(aF[lv][mf][0], aF[lv][mf][1], aF[lv][mf][2], aF[lv][mf][3],
                        sb + tb + sw128(off));
            }
        }
#pragma unroll
        for (int lv = 0; lv < 2; lv++) {
            uint32_t tb = base + (2 + lv) * TILE_B;
#pragma unroll
            for (int nfp = 0; nfp < 2; nfp++) {
                uint32_t off = (uint32_t)((n0w + nfp * 16 + b_lrow) * 128
                                          + (ks * 16 + b_lk8) * 2);
                uint32_t r0, r1, r2, r3;
                ldsm_x4(r0, r1, r2, r3, sb + tb + sw128(off));
                bF[lv][nfp * 2][0] = r0;      bF[lv][nfp * 2][1] = r1;
                bF[lv][nfp * 2 + 1][0] = r2;  bF[lv][nfp * 2 + 1][1] = r3;
            }
        }
        // product 0: A0*B0
#pragma unroll
        for (int mf = 0; mf < 2; mf++)
#pragma unroll
            for (int nf = 0; nf < 4; nf++) mma16816(acc[mf][nf], aF[0][mf], bF[0][nf]);
        // product 1: A0*B1
#pragma unroll
        for (int mf = 0; mf < 2; mf++)
#pragma unroll
            for (int nf = 0; nf < 4; nf++) mma16816(acc[mf][nf], aF[0][mf], bF[1][nf]);
        // product 2: A1*B0
#pragma unroll
        for (int mf = 0; mf < 2; mf++)
#pragma unroll
            for (int nf = 0; nf < 4; nf++) mma16816(acc[mf][nf], aF[1][mf], bF[0][nf]);
    };

    // ---- prologue: fill buffer 0 ----
    {
        float4 av[2], bv[2];
        ldg_sub(0, 0, av, bv);  sts_sub(0, 0, av, bv);
        ldg_sub(0, 1, av, bv);  sts_sub(0, 1, av, bv);
    }
    __syncthreads();

    // ---- main loop ----
    for (int ch = 0; ch < NCH; ch++) {
        const uint32_t cur = (uint32_t)((ch & 1) * BUF_B);
        const uint32_t nxt = (uint32_t)(((ch + 1) & 1) * BUF_B);
        const bool pf = (ch + 1 < NCH);
        float4 av[2], bv[2];

        if (pf) ldg_sub(ch + 1, 0, av, bv);
        mma_ks(cur, 0);
        mma_ks(cur, 1);
        if (pf) sts_sub(nxt, 0, av, bv);

        if (pf) ldg_sub(ch + 1, 1, av, bv);
        mma_ks(cur, 2);
        mma_ks(cur, 3);
        if (pf) sts_sub(nxt, 1, av, bv);

        __syncthreads();
    }

    // ---- epilogue: stage accums -> smem -> coalesced STG (+bias) ----
    float* eps = reinterpret_cast<float*>(smem);   // [128][132]
    const int g = lane >> 2, c = lane & 3;
#pragma unroll
    for (int mf = 0; mf < 2; mf++)
#pragma unroll
        for (int nf = 0; nf < 4; nf++) {
            int r  = m0w + mf * 16 + g;
            int cc = n0w + nf * 8 + 2 * c;
            *reinterpret_cast<float2*>(&eps[r * 132 + cc]) =
                make_float2(acc[mf][nf][0], acc[mf][nf][1]);
            *reinterpret_cast<float2*>(&eps[(r + 8) * 132 + cc]) =
                make_float2(acc[mf][nf][2], acc[mf][nf][3]);
        }
    __syncthreads();

#pragma unroll
    for (int it = 0; it < 8; it++) {
        int idx = tid + it * 512;
        int row = idx >> 5;
        int c4  = (idx & 31) << 2;
        float4 v = *reinterpret_cast<float4*>(&eps[row * 132 + c4]);
        if (bias) {
            float4 bz = *reinterpret_cast<const float4*>(&bias[col0 + c4]);
            v.x += bz.x; v.y += bz.y; v.z += bz.z; v.w += bz.w;
        }
        *reinterpret_cast<float4*>(&Cb[(size_t)(row0 + row) * N + col0 + c4]) = v;
    }
    // second half of rows
#pragma unroll
    for (int it = 8; it < 16; it++) {
        int idx = tid + it * 512;
        if (idx < 128 * 32) break;
    }
    // (128 rows x 32 float4 = 4096 float4 = 512 threads x 8 iters — done above)
}

// ============================================================
// Batched 32x32 transpose: XT[b][d][s] = X[b][s][d]
// ============================================================
__global__ __launch_bounds__(256) void transpose_x(const float* __restrict__ X,
                                                   float* __restrict__ XT)
{
    __shared__ float t[32][33];
    const int b = blockIdx.z;
    const int s0 = blockIdx.x * 32, d0 = blockIdx.y * 32;
    const float* Xb = X + (size_t)b * SS * DD;
    float* Tb = XT + (size_t)b * SS * DD;
    const int tx = threadIdx.x, ty = threadIdx.y;
#pragma unroll
    for (int j = 0; j < 4; j++)
        t[ty + 8 * j][tx] = Xb[(size_t)(s0 + ty + 8 * j) * DD + d0 + tx];
    __syncthreads();
#pragma unroll
    for (int j = 0; j < 4; j++)
        Tb[(size_t)(d0 + ty + 8 * j) * SS + s0 + tx] = t[tx][ty + 8 * j];
}

// ============================================================
// In-place row softmax (rows of length SS = 2048)
// ============================================================
__device__ __forceinline__ float warp_max(float v) {
#pragma unroll
    for (int o = 16; o > 0; o >>= 1) v = fmaxf(v, __shfl_xor_sync(0xFFFFFFFFu, v, o));
    return v;
}
__device__ __forceinline__ float warp_sum(float v) {
#pragma unroll
    for (int o = 16; o > 0; o >>= 1) v += __shfl_xor_sync(0xFFFFFFFFu, v, o);
    return v;
}

__global__ __launch_bounds__(256) void softmax_rows(float* __restrict__ attn)
{
    __shared__ float red[8];
    float* row = attn + (long long)blockIdx.x * SS;
    const int tid = threadIdx.x, lane = tid & 31, wid = tid >> 5;

    float4 v[2];
    v[0] = *reinterpret_cast<const float4*>(&row[tid * 4]);
    v[1] = *reinterpret_cast<const float4*>(&row[(tid + 256) * 4]);

    float mx = -INFINITY;
#pragma unroll
    for (int i = 0; i < 2; i++)
        mx = fmaxf(mx, fmaxf(fmaxf(v[i].x, v[i].y), fmaxf(v[i].z, v[i].w)));
    mx = warp_max(mx);
    if (lane == 0) red[wid] = mx;
    __syncthreads();
    if (wid == 0) {
        float t = (lane < 8) ? red[lane] : -INFINITY;
        t = warp_max(t);
        if (lane == 0) red[0] = t;
    }
    __syncthreads();
    mx = red[0];
    __syncthreads();

    float s = 0.f;
#pragma unroll
    for (int i = 0; i < 2; i++) {
        v[i].x = expf(v[i].x - mx); s += v[i].x;
        v[i].y = expf(v[i].y - mx); s += v[i].y;
        v[i].z = expf(v[i].z - mx); s += v[i].z;
        v[i].w = expf(v[i].w - mx); s += v[i].w;
    }
    s = warp_sum(s);
    if (lane == 0) red[wid] = s;
    __syncthreads();
    if (wid == 0) {
        float t = (lane < 8) ? red[lane] : 0.0f;
        t = warp_sum(t);
        if (lane == 0) red[0] = t;
    }
    __syncthreads();
    float inv = 1.0f / red[0];

#pragma unroll
    for (int i = 0; i < 2; i++) { v[i].x *= inv; v[i].y *= inv; v[i].z *= inv; v[i].w *= inv; }
    *reinterpret_cast<float4*>(&row[tid * 4])         = v[0];
    *reinterpret_cast<float4*>(&row[(tid + 256) * 4]) = v[1];
}

// ============================================================
// kernel_launch
// ============================================================
extern "C" void kernel_launch(void* const* d_in, const int* in_sizes, int n_in,
                              void* d_out, int out_size)
{
    const float* X    = (const float*)d_in[0];
    const float* W    = (const float*)d_in[1];
    const float* bias = (const float*)d_in[2];

    float* ctx  = (float*)d_out;                           // [8,2048,1024]
    float* attn = (float*)d_out + (size_t)BB * SS * DD;    // [8,2048,2048]

    float *proj = nullptr, *xt = nullptr;
    cudaGetSymbolAddress((void**)&proj, g_proj);
    cudaGetSymbolAddress((void**)&xt, g_xt);

    cudaFuncSetAttribute(gemm_nt_mma, cudaFuncAttributeMaxDynamicSharedMemorySize, GEMM_SMEM);

    const long long sXD = (long long)SS * DD;
    const long long sAA = (long long)SS * SS;

    // XT[b] = X[b]^T (GEMM3 in NT form)
    {
        dim3 grid(SS / 32, DD / 32, BB);
        transpose_x<<<grid, dim3(32, 8)>>>(X, xt);
    }
    // GEMM1: proj = X[16384,1024] * W^T + b
    {
        dim3 grid(DD / 128, (BB * SS) / 128, 1);
        gemm_nt_mma<<<grid, 512, GEMM_SMEM>>>(X, W, proj, bias, BB * SS, DD, DD, 0, 0, 0);
    }
    // GEMM2: attn[b] = X[b] * proj[b]^T
    {
        dim3 grid(SS / 128, SS / 128, BB);
        gemm_nt_mma<<<grid, 512, GEMM_SMEM>>>(X, proj, attn, nullptr, SS, SS, DD, sXD, sXD, sAA);
    }
    // Softmax in place
    softmax_rows<<<BB * SS, 256>>>(attn);
    // GEMM3: ctx[b] = attn[b] * XT[b]^T
    {
        dim3 grid(DD / 128, SS / 128, BB);
        gemm_nt_mma<<<grid, 512, GEMM_SMEM>>>(attn, xt, ctx, nullptr, SS, DD, SS, sAA, sXD, sXD);
    }
}